// round 9
// baseline (speedup 1.0000x reference)
#include <cuda_runtime.h>
#include <cuda_bf16.h>
#include <math.h>
#include <stdint.h>

#define HW    2560
#define TT    16
#define HEADS 8
#define DH    64
#define QD    512
#define MTOT  (HW * TT)      // 40960
#define SCALE 0.125f

// ---------------- scratch (device globals: allocation-free) ----------------
__device__ float g_v[(size_t)MTOT * QD];
__device__ __nv_bfloat16 g_xh[(size_t)MTOT * QD];
__device__ __nv_bfloat16 g_xl[(size_t)MTOT * QD];
__device__ __nv_bfloat16 g_qh[(size_t)MTOT * QD];
__device__ __nv_bfloat16 g_ql[(size_t)MTOT * QD];
__device__ __nv_bfloat16 g_kh[(size_t)MTOT * QD];
__device__ __nv_bfloat16 g_kl[(size_t)MTOT * QD];
__device__ __nv_bfloat16 g_ath[(size_t)MTOT * QD];
__device__ __nv_bfloat16 g_atl[(size_t)MTOT * QD];
__device__ __nv_bfloat16 g_wth[(size_t)4 * QD * QD];
__device__ __nv_bfloat16 g_wtl[(size_t)4 * QD * QD];
__device__ float g_qr[(size_t)HW * HEADS * TT * 40];   // QR[b][i][r], stride 40

// ---------------- helpers --------------------------------------------------
__device__ __forceinline__ uint32_t smem_u32(const void* p) {
    uint32_t a;
    asm("{ .reg .u64 t; cvta.to.shared.u64 t, %1; cvt.u32.u64 %0, t; }" : "=r"(a) : "l"(p));
    return a;
}
__device__ __forceinline__ void mma16816(float* d, const uint32_t* a, const uint32_t* b) {
    asm volatile(
        "mma.sync.aligned.m16n8k16.row.col.f32.bf16.bf16.f32 "
        "{%0,%1,%2,%3}, {%4,%5,%6,%7}, {%8,%9}, {%0,%1,%2,%3};"
        : "+f"(d[0]), "+f"(d[1]), "+f"(d[2]), "+f"(d[3])
        : "r"(a[0]), "r"(a[1]), "r"(a[2]), "r"(a[3]), "r"(b[0]), "r"(b[1]));
}
__device__ __forceinline__ void cp16(uint32_t dst, const void* src) {
    asm volatile("cp.async.ca.shared.global [%0], [%1], 16;" :: "r"(dst), "l"(src));
}
#define CP_COMMIT() asm volatile("cp.async.commit_group;" ::: "memory")
#define CP_WAIT1()  asm volatile("cp.async.wait_group 1;" ::: "memory")
#define CP_WAIT0()  asm volatile("cp.async.wait_group 0;" ::: "memory")

// ---------------- split passes ---------------------------------------------
__global__ __launch_bounds__(256)
void split_x(const float* __restrict__ X, __nv_bfloat16* __restrict__ xh,
             __nv_bfloat16* __restrict__ xl) {
    size_t i = (size_t)blockIdx.x * 256 + threadIdx.x;
    float2 a = ((const float2*)X)[i];
    __nv_bfloat16 hx = __float2bfloat16(a.x);
    __nv_bfloat16 hy = __float2bfloat16(a.y);
    __nv_bfloat16 lx = __float2bfloat16(a.x - __bfloat162float(hx));
    __nv_bfloat16 ly = __float2bfloat16(a.y - __bfloat162float(hy));
    ((__nv_bfloat162*)xh)[i] = __halves2bfloat162(hx, hy);
    ((__nv_bfloat162*)xl)[i] = __halves2bfloat162(lx, ly);
}

__global__ __launch_bounds__(256)
void split_w(const float* __restrict__ W0, const float* __restrict__ W1,
             const float* __restrict__ W2, const float* __restrict__ W3,
             __nv_bfloat16* __restrict__ wh, __nv_bfloat16* __restrict__ wl) {
    __shared__ float t[32][33];
    const int w = blockIdx.z;
    const float* W = (w == 0) ? W0 : (w == 1) ? W1 : (w == 2) ? W2 : W3;
    const int tx = threadIdx.x, ty = threadIdx.y;
#pragma unroll
    for (int i = 0; i < 4; i++)
        t[ty + 8 * i][tx] = W[(size_t)(blockIdx.y * 32 + ty + 8 * i) * QD + blockIdx.x * 32 + tx];
    __syncthreads();
#pragma unroll
    for (int i = 0; i < 4; i++) {
        int n = blockIdx.x * 32 + ty + 8 * i;
        int k = blockIdx.y * 32 + tx;
        float v = t[tx][ty + 8 * i];
        __nv_bfloat16 h = __float2bfloat16(v);
        __nv_bfloat16 l = __float2bfloat16(v - __bfloat162float(h));
        size_t o = ((size_t)w * QD + n) * QD + k;
        wh[o] = h;
        wl[o] = l;
    }
}

// ======== double-buffered split-bf16 GEMM, 64x64 warp tiles ================
#define BKC   32
#define SPADW 20                    // smem row stride in words (40 bf16)
#define TILEB (128 * 80)            // 10240 B per tile
#define BUFB  (4 * TILEB)           // 40960 B per stage
#define GDYN  (2 * BUFB)            // 81920 B

__device__ __forceinline__ void gemm_prefetch(
    uint32_t sbase, int b, int kc, int tid, int m0, int n0,
    const __nv_bfloat16* Ah, const __nv_bfloat16* Al,
    const __nv_bfloat16* Bh, const __nv_bfloat16* Bl) {
#pragma unroll
    for (int i = 0; i < 16; i++) {
        int e = tid + i * 128;
        int tile = e >> 9;
        int r    = (e >> 2) & 127;
        int c16  = e & 3;
        uint32_t dst = sbase + b * BUFB + tile * TILEB + r * 80 + c16 * 16;
        const __nv_bfloat16* src;
        if (tile == 0)      src = Ah + (size_t)(m0 + r) * QD + kc * BKC + c16 * 8;
        else if (tile == 1) src = Al + (size_t)(m0 + r) * QD + kc * BKC + c16 * 8;
        else if (tile == 2) src = Bh + (size_t)(n0 + r) * QD + kc * BKC + c16 * 8;
        else                src = Bl + (size_t)(n0 + r) * QD + kc * BKC + c16 * 8;
        cp16(dst, src);
    }
    CP_COMMIT();
}

// mode = base_mode + blockIdx.z: 0 -> split to (qh,ql); 1 -> (kh,kl);
// 2 -> fp32 to fout (no bias); 3 -> fp32 to fout (+bias)
__global__ __launch_bounds__(128)
void gemm_bf(const __nv_bfloat16* __restrict__ Ah, const __nv_bfloat16* __restrict__ Al,
             const __nv_bfloat16* __restrict__ Wth, const __nv_bfloat16* __restrict__ Wtl,
             const float* __restrict__ bias, int base_mode,
             __nv_bfloat16* __restrict__ qh, __nv_bfloat16* __restrict__ ql,
             __nv_bfloat16* __restrict__ kh, __nv_bfloat16* __restrict__ kl,
             float* __restrict__ fout) {
    extern __shared__ char dsm[];
    const uint32_t sbase = smem_u32(dsm);

    const int tid = threadIdx.x;
    const int wid = tid >> 5, lid = tid & 31;
    const int wm = wid & 1, wn = wid >> 1;      // warp grid 2(m) x 2(n)
    const int g = lid >> 2, t = lid & 3;
    const int m0 = blockIdx.y * 128;
    const int n0 = blockIdx.x * 128;
    const int w  = blockIdx.z;
    const int mode = base_mode + w;
    const __nv_bfloat16* Bh = Wth + (size_t)w * QD * QD;
    const __nv_bfloat16* Bl = Wtl + (size_t)w * QD * QD;

    float acc[4][8][4];
#pragma unroll
    for (int mi = 0; mi < 4; mi++)
#pragma unroll
        for (int ni = 0; ni < 8; ni++)
#pragma unroll
            for (int c = 0; c < 4; c++) acc[mi][ni][c] = 0.0f;

    gemm_prefetch(sbase, 0, 0, tid, m0, n0, Ah, Al, Bh, Bl);

    for (int kc = 0; kc < QD / BKC; kc++) {
        const int last = (kc == QD / BKC - 1);
        if (!last) gemm_prefetch(sbase, (kc + 1) & 1, kc + 1, tid, m0, n0, Ah, Al, Bh, Bl);
        if (!last) CP_WAIT1(); else CP_WAIT0();
        __syncthreads();

        const int b = kc & 1;
        const uint32_t* AshW = (const uint32_t*)(dsm + b * BUFB);
        const uint32_t* AslW = (const uint32_t*)(dsm + b * BUFB + TILEB);
        const uint32_t* BshW = (const uint32_t*)(dsm + b * BUFB + 2 * TILEB);
        const uint32_t* BslW = (const uint32_t*)(dsm + b * BUFB + 3 * TILEB);

#pragma unroll
        for (int ks = 0; ks < 2; ks++) {
            const int c0w = ks * 8 + t;
            uint32_t bh[8][2], bl[8][2];
#pragma unroll
            for (int ni = 0; ni < 8; ni++) {
                int n = wn * 64 + ni * 8 + g;
                bh[ni][0] = BshW[n * SPADW + c0w];
                bh[ni][1] = BshW[n * SPADW + c0w + 4];
                bl[ni][0] = BslW[n * SPADW + c0w];
                bl[ni][1] = BslW[n * SPADW + c0w + 4];
            }
#pragma unroll
            for (int mi = 0; mi < 4; mi++) {
                int r = wm * 64 + mi * 16 + g;
                uint32_t ah[4], al[4];
                ah[0] = AshW[r * SPADW + c0w];
                ah[1] = AshW[(r + 8) * SPADW + c0w];
                ah[2] = AshW[r * SPADW + c0w + 4];
                ah[3] = AshW[(r + 8) * SPADW + c0w + 4];
                al[0] = AslW[r * SPADW + c0w];
                al[1] = AslW[(r + 8) * SPADW + c0w];
                al[2] = AslW[r * SPADW + c0w + 4];
                al[3] = AslW[(r + 8) * SPADW + c0w + 4];
#pragma unroll
                for (int ni = 0; ni < 8; ni++) {
                    mma16816(acc[mi][ni], ah, bh[ni]);
                    mma16816(acc[mi][ni], ah, bl[ni]);
                    mma16816(acc[mi][ni], al, bh[ni]);
                }
            }
        }
        __syncthreads();
    }

    // ---- epilogue ----
    if (mode < 2) {
        __nv_bfloat16* oh = (mode == 0) ? qh : kh;
        __nv_bfloat16* ol = (mode == 0) ? ql : kl;
#pragma unroll
        for (int mi = 0; mi < 4; mi++) {
            int r = m0 + wm * 64 + mi * 16 + g;
#pragma unroll
            for (int ni = 0; ni < 8; ni++) {
                int col = n0 + wn * 64 + ni * 8 + t * 2;
#pragma unroll
                for (int half = 0; half < 2; half++) {
                    int rr = r + half * 8;
                    float v0 = acc[mi][ni][half * 2], v1 = acc[mi][ni][half * 2 + 1];
                    __nv_bfloat16 h0 = __float2bfloat16(v0);
                    __nv_bfloat16 h1 = __float2bfloat16(v1);
                    __nv_bfloat16 l0 = __float2bfloat16(v0 - __bfloat162float(h0));
                    __nv_bfloat16 l1 = __float2bfloat16(v1 - __bfloat162float(h1));
                    *(__nv_bfloat162*)&oh[(size_t)rr * QD + col] = __halves2bfloat162(h0, h1);
                    *(__nv_bfloat162*)&ol[(size_t)rr * QD + col] = __halves2bfloat162(l0, l1);
                }
            }
        }
    } else {
#pragma unroll
        for (int mi = 0; mi < 4; mi++) {
            int r = m0 + wm * 64 + mi * 16 + g;
#pragma unroll
            for (int ni = 0; ni < 8; ni++) {
                int col = n0 + wn * 64 + ni * 8 + t * 2;
                float b0 = 0.f, b1 = 0.f;
                if (mode == 3) { b0 = bias[col]; b1 = bias[col + 1]; }
                float2 v0, v1;
                v0.x = acc[mi][ni][0] + b0; v0.y = acc[mi][ni][1] + b1;
                v1.x = acc[mi][ni][2] + b0; v1.y = acc[mi][ni][3] + b1;
                *(float2*)&fout[(size_t)r * QD + col] = v0;
                *(float2*)&fout[(size_t)(r + 8) * QD + col] = v1;
            }
        }
    }
}

// ======== qrel kernel: QR[b,i,r] = sum_d q[b,i,d] * rel_k[r,d] =============
__global__ __launch_bounds__(128)
void qrel_k(const __nv_bfloat16* __restrict__ qh, const __nv_bfloat16* __restrict__ ql,
            const float* __restrict__ RK, float* __restrict__ QR) {
    __shared__ __nv_bfloat16 rh[40 * 72];
    __shared__ __nv_bfloat16 rl[40 * 72];
    const int tid = threadIdx.x;
    const int lid = tid & 31;
    const int g = lid >> 2, t = lid & 3;
    const int h = blockIdx.y;
    const int m0 = blockIdx.x * 128 + (tid >> 5) * 32;   // warp's 32 rows

    for (int e = tid; e < 33 * 64; e += 128) {
        int r = e >> 6, d = e & 63;
        float v = RK[e];
        __nv_bfloat16 hh = __float2bfloat16(v);
        rh[r * 72 + d] = hh;
        rl[r * 72 + d] = __float2bfloat16(v - __bfloat162float(hh));
    }
    __syncthreads();

    const uint32_t* rhW = (const uint32_t*)rh;
    const uint32_t* rlW = (const uint32_t*)rl;

    float acc[2][5][4];
#pragma unroll
    for (int mf = 0; mf < 2; mf++)
#pragma unroll
        for (int nf = 0; nf < 5; nf++)
#pragma unroll
            for (int c = 0; c < 4; c++) acc[mf][nf][c] = 0.0f;

#pragma unroll
    for (int ks = 0; ks < 4; ks++) {
        uint32_t ah[2][4], al[2][4];
#pragma unroll
        for (int mf = 0; mf < 2; mf++) {
            size_t base = (size_t)(m0 + mf * 16 + g) * QD + h * 64 + ks * 16 + t * 2;
            ah[mf][0] = *(const uint32_t*)&qh[base];
            ah[mf][1] = *(const uint32_t*)&qh[base + (size_t)8 * QD];
            ah[mf][2] = *(const uint32_t*)&qh[base + 8];
            ah[mf][3] = *(const uint32_t*)&qh[base + (size_t)8 * QD + 8];
            al[mf][0] = *(const uint32_t*)&ql[base];
            al[mf][1] = *(const uint32_t*)&ql[base + (size_t)8 * QD];
            al[mf][2] = *(const uint32_t*)&ql[base + 8];
            al[mf][3] = *(const uint32_t*)&ql[base + (size_t)8 * QD + 8];
        }
        const int w0 = ks * 8 + t;
#pragma unroll
        for (int nf = 0; nf < 5; nf++) {
            int nr = nf * 8 + g;
            uint32_t bh[2] = { rhW[nr * 36 + w0], rhW[nr * 36 + w0 + 4] };
            uint32_t bl[2] = { rlW[nr * 36 + w0], rlW[nr * 36 + w0 + 4] };
#pragma unroll
            for (int mf = 0; mf < 2; mf++) {
                mma16816(acc[mf][nf], ah[mf], bh);
                mma16816(acc[mf][nf], ah[mf], bl);
                mma16816(acc[mf][nf], al[mf], bh);
            }
        }
    }

#pragma unroll
    for (int mf = 0; mf < 2; mf++) {
#pragma unroll
        for (int nf = 0; nf < 5; nf++) {
            int c = nf * 8 + 2 * t;
#pragma unroll
            for (int half = 0; half < 2; half++) {
                int r = m0 + mf * 16 + g + half * 8;
                int hw = r >> 4, tt = r & 15;
                float* dst = QR + (((size_t)hw * 8 + h) * 16 + tt) * 40;
                dst[c]     = acc[mf][nf][half * 2];
                dst[c + 1] = acc[mf][nf][half * 2 + 1];
            }
        }
    }
}

// ======== attention v3: 128 thr, 4 warps = 4 (hw,head) pairs ===============
#define OFFQH 0
#define OFFQL 2304
#define OFFKH 4608
#define OFFKL 6912
#define OFFV  9216
#define OFFS  13568
#define PAIRB 14656
#define OFFRV (4 * PAIRB)                 // 58624
#define ADYN  (OFFRV + 33 * 272 + 16)     // 67616

struct Boxes { int hs[TT]; int ws[TT]; int sub_h; int sub_w; };

__global__ __launch_bounds__(128)
void attn3(const __nv_bfloat16* __restrict__ QH, const __nv_bfloat16* __restrict__ QL,
           const __nv_bfloat16* __restrict__ KH, const __nv_bfloat16* __restrict__ KL,
           const float* __restrict__ V, const float* __restrict__ QR,
           const float* __restrict__ RV,
           __nv_bfloat16* __restrict__ ATH, __nv_bfloat16* __restrict__ ATL,
           Boxes bx) {
    extern __shared__ char as_[];
    const uint32_t sb = smem_u32(as_);
    const int tid = threadIdx.x;
    const int wid = tid >> 5, lid = tid & 31;
    const int g = lid >> 2, t = lid & 3;
    const int hw = blockIdx.x;
    const int head = blockIdx.y * 4 + wid;

    // ---- staging (each warp stages its pair; rvs CTA-wide) ----
    {
        const size_t rb = (size_t)hw * 16 * QD + head * 64;
        const uint32_t pb = sb + wid * PAIRB;
#pragma unroll
        for (int i = 0; i < 4; i++) {
            int c = lid + 32 * i;
            int row = c >> 3, ch = c & 7;
            uint32_t doff = row * 144 + ch * 16;
            size_t soff = rb + (size_t)row * QD + ch * 8;
            cp16(pb + OFFQH + doff, QH + soff);
            cp16(pb + OFFQL + doff, QL + soff);
            cp16(pb + OFFKH + doff, KH + soff);
            cp16(pb + OFFKL + doff, KL + soff);
        }
#pragma unroll
        for (int i = 0; i < 8; i++) {
            int c = lid + 32 * i;
            int row = c >> 4, ch = c & 15;
            cp16(pb + OFFV + row * 272 + ch * 16, V + rb + (size_t)row * QD + ch * 4);
        }
#pragma unroll
        for (int i = 0; i < 5; i++) {
            int c = tid + 128 * i;
            if (c < 528) {
                int row = c >> 4, ch = c & 15;
                cp16(sb + OFFRV + row * 272 + ch * 16, RV + row * 64 + ch * 4);
            }
        }
    }
    CP_COMMIT();
    CP_WAIT0();
    __syncthreads();

    // ---- fg bitmask ----
    const int y = hw / 40, x = hw % 40;
    unsigned fg = 0;
#pragma unroll
    for (int tt = 0; tt < TT; tt++) {
        int inb = (y >= bx.hs[tt]) & (y < bx.hs[tt] + bx.sub_h) &
                  (x >= bx.ws[tt]) & (x < bx.ws[tt] + bx.sub_w);
        fg |= (unsigned)inb << tt;
    }

    // ---- sim = QK^T via split mma ----
    const uint32_t* qhW = (const uint32_t*)(as_ + wid * PAIRB + OFFQH);
    const uint32_t* qlW = (const uint32_t*)(as_ + wid * PAIRB + OFFQL);
    const uint32_t* khW = (const uint32_t*)(as_ + wid * PAIRB + OFFKH);
    const uint32_t* klW = (const uint32_t*)(as_ + wid * PAIRB + OFFKL);

    float sacc[2][4];
#pragma unroll
    for (int nf = 0; nf < 2; nf++)
#pragma unroll
        for (int c = 0; c < 4; c++) sacc[nf][c] = 0.0f;

#pragma unroll
    for (int ks = 0; ks < 4; ks++) {
        const int w0 = ks * 8 + t;
        uint32_t ah[4], al[4];
        ah[0] = qhW[g * 36 + w0];       ah[1] = qhW[(g + 8) * 36 + w0];
        ah[2] = qhW[g * 36 + w0 + 4];   ah[3] = qhW[(g + 8) * 36 + w0 + 4];
        al[0] = qlW[g * 36 + w0];       al[1] = qlW[(g + 8) * 36 + w0];
        al[2] = qlW[g * 36 + w0 + 4];   al[3] = qlW[(g + 8) * 36 + w0 + 4];
#pragma unroll
        for (int nf = 0; nf < 2; nf++) {
            int nr = nf * 8 + g;
            uint32_t bh[2] = { khW[nr * 36 + w0], khW[nr * 36 + w0 + 4] };
            uint32_t bl[2] = { klW[nr * 36 + w0], klW[nr * 36 + w0 + 4] };
            mma16816(sacc[nf], ah, bh);
            mma16816(sacc[nf], ah, bl);
            mma16816(sacc[nf], al, bh);
        }
    }

    // ---- add QR gather, scale, mask ----
    const float* qrp = QR + ((size_t)(hw * 8 + head) * 16) * 40;
#pragma unroll
    for (int nf = 0; nf < 2; nf++) {
        int cb = nf * 8 + 2 * t;
#pragma unroll
        for (int c = 0; c < 4; c++) {
            int row = (c < 2) ? g : g + 8;
            int col = cb + (c & 1);
            float s = sacc[nf][c] + qrp[row * 40 + (col - row + 16)];
            float m = (((fg >> row) & 1u) == ((fg >> col) & 1u)) ? 1.0f : 0.01f;
            sacc[nf][c] = s * SCALE * m;
        }
    }

    // ---- softmax: rows g (regs [nf][0..1]) and g+8 (regs [nf][2..3]) ------
    float mxA = fmaxf(fmaxf(sacc[0][0], sacc[0][1]), fmaxf(sacc[1][0], sacc[1][1]));
    float mxB = fmaxf(fmaxf(sacc[0][2], sacc[0][3]), fmaxf(sacc[1][2], sacc[1][3]));
    mxA = fmaxf(mxA, __shfl_xor_sync(0xffffffffu, mxA, 1));
    mxA = fmaxf(mxA, __shfl_xor_sync(0xffffffffu, mxA, 2));
    mxB = fmaxf(mxB, __shfl_xor_sync(0xffffffffu, mxB, 1));
    mxB = fmaxf(mxB, __shfl_xor_sync(0xffffffffu, mxB, 2));
#pragma unroll
    for (int nf = 0; nf < 2; nf++) {
        sacc[nf][0] = expf(sacc[nf][0] - mxA);
        sacc[nf][1] = expf(sacc[nf][1] - mxA);
        sacc[nf][2] = expf(sacc[nf][2] - mxB);
        sacc[nf][3] = expf(sacc[nf][3] - mxB);
    }
    float smA = sacc[0][0] + sacc[0][1] + sacc[1][0] + sacc[1][1];
    float smB = sacc[0][2] + sacc[0][3] + sacc[1][2] + sacc[1][3];
    smA += __shfl_xor_sync(0xffffffffu, smA, 1);
    smA += __shfl_xor_sync(0xffffffffu, smA, 2);
    smB += __shfl_xor_sync(0xffffffffu, smB, 1);
    smB += __shfl_xor_sync(0xffffffffu, smB, 2);
    const float ivA = 1.0f / smA, ivB = 1.0f / smB;

    // ---- store probs to sims[16][17] ----
    float* simsP = (float*)(as_ + wid * PAIRB + OFFS);
#pragma unroll
    for (int nf = 0; nf < 2; nf++) {
        int cb = nf * 8 + 2 * t;
        simsP[g * 17 + cb]           = sacc[nf][0] * ivA;
        simsP[g * 17 + cb + 1]       = sacc[nf][1] * ivA;
        simsP[(g + 8) * 17 + cb]     = sacc[nf][2] * ivB;
        simsP[(g + 8) * 17 + cb + 1] = sacc[nf][3] * ivB;
    }
    __syncthreads();

    // ---- out = P @ (V + RVgather), CTA-cooperative -----------------------
    const float* rvP = (const float*)(as_ + OFFRV);
    const int oi = tid >> 3, od8 = tid & 7;
#pragma unroll
    for (int p = 0; p < 4; p++) {
        const float* vsP = (const float*)(as_ + p * PAIRB + OFFV);
        const float* siP = (const float*)(as_ + p * PAIRB + OFFS);
        float o[8];
#pragma unroll
        for (int c = 0; c < 8; c++) o[c] = 0.0f;
#pragma unroll
        for (int j = 0; j < 16; j++) {
            float s = siP[oi * 17 + j];
            const float4* vr = (const float4*)(vsP + j * 68 + od8 * 8);
            const float4* rr = (const float4*)(rvP + (j - oi + 16) * 68 + od8 * 8);
            float4 v0 = vr[0], v1 = vr[1];
            float4 r0 = rr[0], r1 = rr[1];
            o[0] = fmaf(s, v0.x + r0.x, o[0]);
            o[1] = fmaf(s, v0.y + r0.y, o[1]);
            o[2] = fmaf(s, v0.z + r0.z, o[2]);
            o[3] = fmaf(s, v0.w + r0.w, o[3]);
            o[4] = fmaf(s, v1.x + r1.x, o[4]);
            o[5] = fmaf(s, v1.y + r1.y, o[5]);
            o[6] = fmaf(s, v1.z + r1.z, o[6]);
            o[7] = fmaf(s, v1.w + r1.w, o[7]);
        }
        int hd = blockIdx.y * 4 + p;
        size_t ob = ((size_t)hw * 16 + oi) * QD + hd * 64 + od8 * 8;
#pragma unroll
        for (int c = 0; c < 4; c++) {
            float v0 = o[2 * c], v1 = o[2 * c + 1];
            __nv_bfloat16 h0 = __float2bfloat16(v0);
            __nv_bfloat16 h1 = __float2bfloat16(v1);
            __nv_bfloat16 l0 = __float2bfloat16(v0 - __bfloat162float(h0));
            __nv_bfloat16 l1 = __float2bfloat16(v1 - __bfloat162float(h1));
            *(__nv_bfloat162*)&ATH[ob + 2 * c] = __halves2bfloat162(h0, h1);
            *(__nv_bfloat162*)&ATL[ob + 2 * c] = __halves2bfloat162(l0, l1);
        }
    }
}

// ---------------------------- launcher -------------------------------------
extern "C" void kernel_launch(void* const* d_in, const int* in_sizes, int n_in,
                              void* d_out, int out_size) {
    const float* x     = (const float*)d_in[0];
    const float* Wq    = (const float*)d_in[1];
    const float* Wk    = (const float*)d_in[2];
    const float* Wv    = (const float*)d_in[3];
    const float* Wo    = (const float*)d_in[4];
    const float* bo    = (const float*)d_in[5];
    const float* rel_k = (const float*)d_in[6];
    const float* rel_v = (const float*)d_in[7];
    float* out = (float*)d_out;

    float *v, *qr;
    __nv_bfloat16 *xh, *xl, *qh, *ql, *kh, *kl, *ath, *atl, *wth, *wtl;
    cudaGetSymbolAddress((void**)&v,   g_v);
    cudaGetSymbolAddress((void**)&qr,  g_qr);
    cudaGetSymbolAddress((void**)&xh,  g_xh);
    cudaGetSymbolAddress((void**)&xl,  g_xl);
    cudaGetSymbolAddress((void**)&qh,  g_qh);
    cudaGetSymbolAddress((void**)&ql,  g_ql);
    cudaGetSymbolAddress((void**)&kh,  g_kh);
    cudaGetSymbolAddress((void**)&kl,  g_kl);
    cudaGetSymbolAddress((void**)&ath, g_ath);
    cudaGetSymbolAddress((void**)&atl, g_atl);
    cudaGetSymbolAddress((void**)&wth, g_wth);
    cudaGetSymbolAddress((void**)&wtl, g_wtl);

    // Box path (exact binary64 semantics): SUB_H=15, SUB_W=9
    Boxes bx;
    bx.sub_h = (int)((0.35 - 0.10) * 64.0);
    bx.sub_w = (int)((0.35 - 0.10) * 40.0);
    for (int t = 0; t < TT; t++) {
        double r  = (double)t / 15.0;
        double h0 = 0.10 + r * (0.60 - 0.10);
        double w0 = 0.10 + r * (0.60 - 0.10);
        bx.hs[t] = (int)(h0 * 64.0);
        bx.ws[t] = (int)(w0 * 40.0);
    }

    cudaFuncSetAttribute(gemm_bf, cudaFuncAttributeMaxDynamicSharedMemorySize, GDYN);
    cudaFuncSetAttribute(attn3,   cudaFuncAttributeMaxDynamicSharedMemorySize, ADYN);

    split_x<<<MTOT * QD / 512, 256>>>(x, xh, xl);
    split_w<<<dim3(16, 16, 4), dim3(32, 8)>>>(Wq, Wk, Wv, Wo, wth, wtl);

    // fused QKV: z=0 -> q split, z=1 -> k split, z=2 -> v fp32
    gemm_bf<<<dim3(4, 320, 3), 128, GDYN>>>(xh, xl, wth, wtl, nullptr, 0,
                                            qh, ql, kh, kl, v);

    qrel_k<<<dim3(320, 8), 128>>>(qh, ql, rel_k, qr);

    attn3<<<dim3(HW, 2), 128, ADYN>>>(qh, ql, kh, kl, v, qr, rel_v, ath, atl, bx);

    // output projection: weight index 3 (pre-offset), mode 3 (fp32 + bias)
    gemm_bf<<<dim3(4, 320, 1), 128, GDYN>>>(ath, atl,
                                            wth + (size_t)3 * QD * QD,
                                            wtl + (size_t)3 * QD * QD,
                                            bo, 3, nullptr, nullptr, nullptr, nullptr, out);
}

// round 10
// speedup vs baseline: 1.4458x; 1.4458x over previous
#include <cuda_runtime.h>
#include <cuda_bf16.h>
#include <math.h>
#include <stdint.h>

#define HW    2560
#define TT    16
#define HEADS 8
#define DH    64
#define QD    512
#define MTOT  (HW * TT)      // 40960
#define SCALE 0.125f

// ---------------- scratch (device globals: allocation-free) ----------------
__device__ float g_v[(size_t)MTOT * QD];
__device__ __nv_bfloat16 g_xh[(size_t)MTOT * QD];
__device__ __nv_bfloat16 g_xl[(size_t)MTOT * QD];
__device__ __nv_bfloat16 g_qh[(size_t)MTOT * QD];
__device__ __nv_bfloat16 g_ql[(size_t)MTOT * QD];
__device__ __nv_bfloat16 g_kh[(size_t)MTOT * QD];
__device__ __nv_bfloat16 g_kl[(size_t)MTOT * QD];
__device__ __nv_bfloat16 g_ath[(size_t)MTOT * QD];
__device__ __nv_bfloat16 g_atl[(size_t)MTOT * QD];
__device__ __nv_bfloat16 g_wth[(size_t)4 * QD * QD];
__device__ __nv_bfloat16 g_wtl[(size_t)4 * QD * QD];
__device__ float g_qr[(size_t)HW * HEADS * TT * 40];   // QR[b][i][r], stride 40

// ---------------- helpers --------------------------------------------------
__device__ __forceinline__ uint32_t smem_u32(const void* p) {
    uint32_t a;
    asm("{ .reg .u64 t; cvta.to.shared.u64 t, %1; cvt.u32.u64 %0, t; }" : "=r"(a) : "l"(p));
    return a;
}
__device__ __forceinline__ void mma16816(float* d, const uint32_t* a, const uint32_t* b) {
    asm volatile(
        "mma.sync.aligned.m16n8k16.row.col.f32.bf16.bf16.f32 "
        "{%0,%1,%2,%3}, {%4,%5,%6,%7}, {%8,%9}, {%0,%1,%2,%3};"
        : "+f"(d[0]), "+f"(d[1]), "+f"(d[2]), "+f"(d[3])
        : "r"(a[0]), "r"(a[1]), "r"(a[2]), "r"(a[3]), "r"(b[0]), "r"(b[1]));
}
__device__ __forceinline__ void cp16(uint32_t dst, const void* src) {
    asm volatile("cp.async.ca.shared.global [%0], [%1], 16;" :: "r"(dst), "l"(src));
}
#define CP_COMMIT() asm volatile("cp.async.commit_group;" ::: "memory")
#define CP_WAIT1()  asm volatile("cp.async.wait_group 1;" ::: "memory")
#define CP_WAIT0()  asm volatile("cp.async.wait_group 0;" ::: "memory")

// ---------------- split passes ---------------------------------------------
__global__ __launch_bounds__(256)
void split_x(const float* __restrict__ X, __nv_bfloat16* __restrict__ xh,
             __nv_bfloat16* __restrict__ xl) {
    size_t i = (size_t)blockIdx.x * 256 + threadIdx.x;
    float2 a = ((const float2*)X)[i];
    __nv_bfloat16 hx = __float2bfloat16(a.x);
    __nv_bfloat16 hy = __float2bfloat16(a.y);
    __nv_bfloat16 lx = __float2bfloat16(a.x - __bfloat162float(hx));
    __nv_bfloat16 ly = __float2bfloat16(a.y - __bfloat162float(hy));
    ((__nv_bfloat162*)xh)[i] = __halves2bfloat162(hx, hy);
    ((__nv_bfloat162*)xl)[i] = __halves2bfloat162(lx, ly);
}

__global__ __launch_bounds__(256)
void split_w(const float* __restrict__ W0, const float* __restrict__ W1,
             const float* __restrict__ W2, const float* __restrict__ W3,
             __nv_bfloat16* __restrict__ wh, __nv_bfloat16* __restrict__ wl) {
    __shared__ float t[32][33];
    const int w = blockIdx.z;
    const float* W = (w == 0) ? W0 : (w == 1) ? W1 : (w == 2) ? W2 : W3;
    const int tx = threadIdx.x, ty = threadIdx.y;
#pragma unroll
    for (int i = 0; i < 4; i++)
        t[ty + 8 * i][tx] = W[(size_t)(blockIdx.y * 32 + ty + 8 * i) * QD + blockIdx.x * 32 + tx];
    __syncthreads();
#pragma unroll
    for (int i = 0; i < 4; i++) {
        int n = blockIdx.x * 32 + ty + 8 * i;
        int k = blockIdx.y * 32 + tx;
        float v = t[tx][ty + 8 * i];
        __nv_bfloat16 h = __float2bfloat16(v);
        __nv_bfloat16 l = __float2bfloat16(v - __bfloat162float(h));
        size_t o = ((size_t)w * QD + n) * QD + k;
        wh[o] = h;
        wl[o] = l;
    }
}

// ======== double-buffered split-bf16 GEMM (R8 mainloop, 256 thr) ===========
#define BKC   32
#define SPADW 20                    // smem row stride in words (40 bf16)
#define TILEB (128 * 80)            // 10240 B per tile
#define BUFB  (4 * TILEB)           // 40960 B per stage
#define GDYN  (2 * BUFB)            // 81920 B

__device__ __forceinline__ void gemm_prefetch(
    uint32_t sbase, int b, int kc, int tid, int m0, int n0,
    const __nv_bfloat16* Ah, const __nv_bfloat16* Al,
    const __nv_bfloat16* Bh, const __nv_bfloat16* Bl) {
#pragma unroll
    for (int i = 0; i < 8; i++) {
        int e = tid + i * 256;
        int tile = e >> 9;
        int r    = (e >> 2) & 127;
        int c16  = e & 3;
        uint32_t dst = sbase + b * BUFB + tile * TILEB + r * 80 + c16 * 16;
        const __nv_bfloat16* src;
        if (tile == 0)      src = Ah + (size_t)(m0 + r) * QD + kc * BKC + c16 * 8;
        else if (tile == 1) src = Al + (size_t)(m0 + r) * QD + kc * BKC + c16 * 8;
        else if (tile == 2) src = Bh + (size_t)(n0 + r) * QD + kc * BKC + c16 * 8;
        else                src = Bl + (size_t)(n0 + r) * QD + kc * BKC + c16 * 8;
        cp16(dst, src);
    }
    CP_COMMIT();
}

// mode = base_mode + blockIdx.z: 0 -> split to (qh,ql); 1 -> (kh,kl);
// 2 -> fp32 to fout (no bias); 3 -> fp32 to fout (+bias)
__global__ __launch_bounds__(256, 2)
void gemm_bf(const __nv_bfloat16* __restrict__ Ah, const __nv_bfloat16* __restrict__ Al,
             const __nv_bfloat16* __restrict__ Wth, const __nv_bfloat16* __restrict__ Wtl,
             const float* __restrict__ bias, int base_mode,
             __nv_bfloat16* __restrict__ qh, __nv_bfloat16* __restrict__ ql,
             __nv_bfloat16* __restrict__ kh, __nv_bfloat16* __restrict__ kl,
             float* __restrict__ fout) {
    extern __shared__ char dsm[];
    const uint32_t sbase = smem_u32(dsm);

    const int tid = threadIdx.x;
    const int wid = tid >> 5, lid = tid & 31;
    const int wm = wid & 3, wn = wid >> 2;      // warp grid 4(m) x 2(n)
    const int g = lid >> 2, t = lid & 3;
    const int m0 = blockIdx.y * 128;
    const int n0 = blockIdx.x * 128;
    const int w  = blockIdx.z;
    const int mode = base_mode + w;
    const __nv_bfloat16* Bh = Wth + (size_t)w * QD * QD;
    const __nv_bfloat16* Bl = Wtl + (size_t)w * QD * QD;

    float acc[2][8][4];
#pragma unroll
    for (int mi = 0; mi < 2; mi++)
#pragma unroll
        for (int ni = 0; ni < 8; ni++)
#pragma unroll
            for (int c = 0; c < 4; c++) acc[mi][ni][c] = 0.0f;

    gemm_prefetch(sbase, 0, 0, tid, m0, n0, Ah, Al, Bh, Bl);

    for (int kc = 0; kc < QD / BKC; kc++) {
        const int last = (kc == QD / BKC - 1);
        if (!last) gemm_prefetch(sbase, (kc + 1) & 1, kc + 1, tid, m0, n0, Ah, Al, Bh, Bl);
        if (!last) CP_WAIT1(); else CP_WAIT0();
        __syncthreads();

        const int b = kc & 1;
        const uint32_t* AshW = (const uint32_t*)(dsm + b * BUFB);
        const uint32_t* AslW = (const uint32_t*)(dsm + b * BUFB + TILEB);
        const uint32_t* BshW = (const uint32_t*)(dsm + b * BUFB + 2 * TILEB);
        const uint32_t* BslW = (const uint32_t*)(dsm + b * BUFB + 3 * TILEB);

#pragma unroll
        for (int ks = 0; ks < 2; ks++) {
            const int c0w = ks * 8 + t;
            uint32_t bh[8][2], bl[8][2];
#pragma unroll
            for (int ni = 0; ni < 8; ni++) {
                int n = wn * 64 + ni * 8 + g;
                bh[ni][0] = BshW[n * SPADW + c0w];
                bh[ni][1] = BshW[n * SPADW + c0w + 4];
                bl[ni][0] = BslW[n * SPADW + c0w];
                bl[ni][1] = BslW[n * SPADW + c0w + 4];
            }
#pragma unroll
            for (int mi = 0; mi < 2; mi++) {
                int r = wm * 32 + mi * 16 + g;
                uint32_t ah[4], al[4];
                ah[0] = AshW[r * SPADW + c0w];
                ah[1] = AshW[(r + 8) * SPADW + c0w];
                ah[2] = AshW[r * SPADW + c0w + 4];
                ah[3] = AshW[(r + 8) * SPADW + c0w + 4];
                al[0] = AslW[r * SPADW + c0w];
                al[1] = AslW[(r + 8) * SPADW + c0w];
                al[2] = AslW[r * SPADW + c0w + 4];
                al[3] = AslW[(r + 8) * SPADW + c0w + 4];
#pragma unroll
                for (int ni = 0; ni < 8; ni++) {
                    mma16816(acc[mi][ni], ah, bh[ni]);
                    mma16816(acc[mi][ni], ah, bl[ni]);
                    mma16816(acc[mi][ni], al, bh[ni]);
                }
            }
        }
        __syncthreads();
    }

    // ---- epilogue ----
    if (mode < 2) {
        __nv_bfloat16* oh = (mode == 0) ? qh : kh;
        __nv_bfloat16* ol = (mode == 0) ? ql : kl;
#pragma unroll
        for (int mi = 0; mi < 2; mi++) {
            int r = m0 + wm * 32 + mi * 16 + g;
#pragma unroll
            for (int ni = 0; ni < 8; ni++) {
                int col = n0 + wn * 64 + ni * 8 + t * 2;
#pragma unroll
                for (int half = 0; half < 2; half++) {
                    int rr = r + half * 8;
                    float v0 = acc[mi][ni][half * 2], v1 = acc[mi][ni][half * 2 + 1];
                    __nv_bfloat16 h0 = __float2bfloat16(v0);
                    __nv_bfloat16 h1 = __float2bfloat16(v1);
                    __nv_bfloat16 l0 = __float2bfloat16(v0 - __bfloat162float(h0));
                    __nv_bfloat16 l1 = __float2bfloat16(v1 - __bfloat162float(h1));
                    *(__nv_bfloat162*)&oh[(size_t)rr * QD + col] = __halves2bfloat162(h0, h1);
                    *(__nv_bfloat162*)&ol[(size_t)rr * QD + col] = __halves2bfloat162(l0, l1);
                }
            }
        }
    } else {
#pragma unroll
        for (int mi = 0; mi < 2; mi++) {
            int r = m0 + wm * 32 + mi * 16 + g;
#pragma unroll
            for (int ni = 0; ni < 8; ni++) {
                int col = n0 + wn * 64 + ni * 8 + t * 2;
                float b0 = 0.f, b1 = 0.f;
                if (mode == 3) { b0 = bias[col]; b1 = bias[col + 1]; }
                float2 v0, v1;
                v0.x = acc[mi][ni][0] + b0; v0.y = acc[mi][ni][1] + b1;
                v1.x = acc[mi][ni][2] + b0; v1.y = acc[mi][ni][3] + b1;
                *(float2*)&fout[(size_t)r * QD + col] = v0;
                *(float2*)&fout[(size_t)(r + 8) * QD + col] = v1;
            }
        }
    }
}

// ======== qrel kernel: QR[b,i,r] = sum_d q[b,i,d] * rel_k[r,d] =============
__global__ __launch_bounds__(128)
void qrel_k(const __nv_bfloat16* __restrict__ qh, const __nv_bfloat16* __restrict__ ql,
            const float* __restrict__ RK, float* __restrict__ QR) {
    __shared__ __nv_bfloat16 rh[40 * 72];
    __shared__ __nv_bfloat16 rl[40 * 72];
    const int tid = threadIdx.x;
    const int lid = tid & 31;
    const int g = lid >> 2, t = lid & 3;
    const int h = blockIdx.y;
    const int m0 = blockIdx.x * 128 + (tid >> 5) * 32;

    for (int e = tid; e < 33 * 64; e += 128) {
        int r = e >> 6, d = e & 63;
        float v = RK[e];
        __nv_bfloat16 hh = __float2bfloat16(v);
        rh[r * 72 + d] = hh;
        rl[r * 72 + d] = __float2bfloat16(v - __bfloat162float(hh));
    }
    __syncthreads();

    const uint32_t* rhW = (const uint32_t*)rh;
    const uint32_t* rlW = (const uint32_t*)rl;

    float acc[2][5][4];
#pragma unroll
    for (int mf = 0; mf < 2; mf++)
#pragma unroll
        for (int nf = 0; nf < 5; nf++)
#pragma unroll
            for (int c = 0; c < 4; c++) acc[mf][nf][c] = 0.0f;

#pragma unroll
    for (int ks = 0; ks < 4; ks++) {
        uint32_t ah[2][4], al[2][4];
#pragma unroll
        for (int mf = 0; mf < 2; mf++) {
            size_t base = (size_t)(m0 + mf * 16 + g) * QD + h * 64 + ks * 16 + t * 2;
            ah[mf][0] = *(const uint32_t*)&qh[base];
            ah[mf][1] = *(const uint32_t*)&qh[base + (size_t)8 * QD];
            ah[mf][2] = *(const uint32_t*)&qh[base + 8];
            ah[mf][3] = *(const uint32_t*)&qh[base + (size_t)8 * QD + 8];
            al[mf][0] = *(const uint32_t*)&ql[base];
            al[mf][1] = *(const uint32_t*)&ql[base + (size_t)8 * QD];
            al[mf][2] = *(const uint32_t*)&ql[base + 8];
            al[mf][3] = *(const uint32_t*)&ql[base + (size_t)8 * QD + 8];
        }
        const int w0 = ks * 8 + t;
#pragma unroll
        for (int nf = 0; nf < 5; nf++) {
            int nr = nf * 8 + g;
            uint32_t bh[2] = { rhW[nr * 36 + w0], rhW[nr * 36 + w0 + 4] };
            uint32_t bl[2] = { rlW[nr * 36 + w0], rlW[nr * 36 + w0 + 4] };
#pragma unroll
            for (int mf = 0; mf < 2; mf++) {
                mma16816(acc[mf][nf], ah[mf], bh);
                mma16816(acc[mf][nf], ah[mf], bl);
                mma16816(acc[mf][nf], al[mf], bh);
            }
        }
    }

#pragma unroll
    for (int mf = 0; mf < 2; mf++) {
#pragma unroll
        for (int nf = 0; nf < 5; nf++) {
            int c = nf * 8 + 2 * t;
#pragma unroll
            for (int half = 0; half < 2; half++) {
                int r = m0 + mf * 16 + g + half * 8;
                int hw = r >> 4, tt = r & 15;
                float* dst = QR + (((size_t)hw * 8 + h) * 16 + tt) * 40;
                dst[c]     = acc[mf][nf][half * 2];
                dst[c + 1] = acc[mf][nf][half * 2 + 1];
            }
        }
    }
}

// ======== attention v3: 128 thr, 4 warps = 4 (hw,head) pairs ===============
#define OFFQH 0
#define OFFQL 2304
#define OFFKH 4608
#define OFFKL 6912
#define OFFV  9216
#define OFFS  13568
#define PAIRB 14656
#define OFFRV (4 * PAIRB)                 // 58624
#define ADYN  (OFFRV + 33 * 272 + 16)     // 67616

struct Boxes { int hs[TT]; int ws[TT]; int sub_h; int sub_w; };

__global__ __launch_bounds__(128)
void attn3(const __nv_bfloat16* __restrict__ QH, const __nv_bfloat16* __restrict__ QL,
           const __nv_bfloat16* __restrict__ KH, const __nv_bfloat16* __restrict__ KL,
           const float* __restrict__ V, const float* __restrict__ QR,
           const float* __restrict__ RV,
           __nv_bfloat16* __restrict__ ATH, __nv_bfloat16* __restrict__ ATL,
           Boxes bx) {
    extern __shared__ char as_[];
    const uint32_t sb = smem_u32(as_);
    const int tid = threadIdx.x;
    const int wid = tid >> 5, lid = tid & 31;
    const int g = lid >> 2, t = lid & 3;
    const int hw = blockIdx.x;
    const int head = blockIdx.y * 4 + wid;

    {
        const size_t rb = (size_t)hw * 16 * QD + head * 64;
        const uint32_t pb = sb + wid * PAIRB;
#pragma unroll
        for (int i = 0; i < 4; i++) {
            int c = lid + 32 * i;
            int row = c >> 3, ch = c & 7;
            uint32_t doff = row * 144 + ch * 16;
            size_t soff = rb + (size_t)row * QD + ch * 8;
            cp16(pb + OFFQH + doff, QH + soff);
            cp16(pb + OFFQL + doff, QL + soff);
            cp16(pb + OFFKH + doff, KH + soff);
            cp16(pb + OFFKL + doff, KL + soff);
        }
#pragma unroll
        for (int i = 0; i < 8; i++) {
            int c = lid + 32 * i;
            int row = c >> 4, ch = c & 15;
            cp16(pb + OFFV + row * 272 + ch * 16, V + rb + (size_t)row * QD + ch * 4);
        }
#pragma unroll
        for (int i = 0; i < 5; i++) {
            int c = tid + 128 * i;
            if (c < 528) {
                int row = c >> 4, ch = c & 15;
                cp16(sb + OFFRV + row * 272 + ch * 16, RV + row * 64 + ch * 4);
            }
        }
    }
    CP_COMMIT();
    CP_WAIT0();
    __syncthreads();

    const int y = hw / 40, x = hw % 40;
    unsigned fg = 0;
#pragma unroll
    for (int tt = 0; tt < TT; tt++) {
        int inb = (y >= bx.hs[tt]) & (y < bx.hs[tt] + bx.sub_h) &
                  (x >= bx.ws[tt]) & (x < bx.ws[tt] + bx.sub_w);
        fg |= (unsigned)inb << tt;
    }

    const uint32_t* qhW = (const uint32_t*)(as_ + wid * PAIRB + OFFQH);
    const uint32_t* qlW = (const uint32_t*)(as_ + wid * PAIRB + OFFQL);
    const uint32_t* khW = (const uint32_t*)(as_ + wid * PAIRB + OFFKH);
    const uint32_t* klW = (const uint32_t*)(as_ + wid * PAIRB + OFFKL);

    float sacc[2][4];
#pragma unroll
    for (int nf = 0; nf < 2; nf++)
#pragma unroll
        for (int c = 0; c < 4; c++) sacc[nf][c] = 0.0f;

#pragma unroll
    for (int ks = 0; ks < 4; ks++) {
        const int w0 = ks * 8 + t;
        uint32_t ah[4], al[4];
        ah[0] = qhW[g * 36 + w0];       ah[1] = qhW[(g + 8) * 36 + w0];
        ah[2] = qhW[g * 36 + w0 + 4];   ah[3] = qhW[(g + 8) * 36 + w0 + 4];
        al[0] = qlW[g * 36 + w0];       al[1] = qlW[(g + 8) * 36 + w0];
        al[2] = qlW[g * 36 + w0 + 4];   al[3] = qlW[(g + 8) * 36 + w0 + 4];
#pragma unroll
        for (int nf = 0; nf < 2; nf++) {
            int nr = nf * 8 + g;
            uint32_t bh[2] = { khW[nr * 36 + w0], khW[nr * 36 + w0 + 4] };
            uint32_t bl[2] = { klW[nr * 36 + w0], klW[nr * 36 + w0 + 4] };
            mma16816(sacc[nf], ah, bh);
            mma16816(sacc[nf], ah, bl);
            mma16816(sacc[nf], al, bh);
        }
    }

    const float* qrp = QR + ((size_t)(hw * 8 + head) * 16) * 40;
#pragma unroll
    for (int nf = 0; nf < 2; nf++) {
        int cb = nf * 8 + 2 * t;
#pragma unroll
        for (int c = 0; c < 4; c++) {
            int row = (c < 2) ? g : g + 8;
            int col = cb + (c & 1);
            float s = sacc[nf][c] + qrp[row * 40 + (col - row + 16)];
            float m = (((fg >> row) & 1u) == ((fg >> col) & 1u)) ? 1.0f : 0.01f;
            sacc[nf][c] = s * SCALE * m;
        }
    }

    float mxA = fmaxf(fmaxf(sacc[0][0], sacc[0][1]), fmaxf(sacc[1][0], sacc[1][1]));
    float mxB = fmaxf(fmaxf(sacc[0][2], sacc[0][3]), fmaxf(sacc[1][2], sacc[1][3]));
    mxA = fmaxf(mxA, __shfl_xor_sync(0xffffffffu, mxA, 1));
    mxA = fmaxf(mxA, __shfl_xor_sync(0xffffffffu, mxA, 2));
    mxB = fmaxf(mxB, __shfl_xor_sync(0xffffffffu, mxB, 1));
    mxB = fmaxf(mxB, __shfl_xor_sync(0xffffffffu, mxB, 2));
#pragma unroll
    for (int nf = 0; nf < 2; nf++) {
        sacc[nf][0] = expf(sacc[nf][0] - mxA);
        sacc[nf][1] = expf(sacc[nf][1] - mxA);
        sacc[nf][2] = expf(sacc[nf][2] - mxB);
        sacc[nf][3] = expf(sacc[nf][3] - mxB);
    }
    float smA = sacc[0][0] + sacc[0][1] + sacc[1][0] + sacc[1][1];
    float smB = sacc[0][2] + sacc[0][3] + sacc[1][2] + sacc[1][3];
    smA += __shfl_xor_sync(0xffffffffu, smA, 1);
    smA += __shfl_xor_sync(0xffffffffu, smA, 2);
    smB += __shfl_xor_sync(0xffffffffu, smB, 1);
    smB += __shfl_xor_sync(0xffffffffu, smB, 2);
    const float ivA = 1.0f / smA, ivB = 1.0f / smB;

    float* simsP = (float*)(as_ + wid * PAIRB + OFFS);
#pragma unroll
    for (int nf = 0; nf < 2; nf++) {
        int cb = nf * 8 + 2 * t;
        simsP[g * 17 + cb]           = sacc[nf][0] * ivA;
        simsP[g * 17 + cb + 1]       = sacc[nf][1] * ivA;
        simsP[(g + 8) * 17 + cb]     = sacc[nf][2] * ivB;
        simsP[(g + 8) * 17 + cb + 1] = sacc[nf][3] * ivB;
    }
    __syncthreads();

    const float* rvP = (const float*)(as_ + OFFRV);
    const int oi = tid >> 3, od8 = tid & 7;
#pragma unroll
    for (int p = 0; p < 4; p++) {
        const float* vsP = (const float*)(as_ + p * PAIRB + OFFV);
        const float* siP = (const float*)(as_ + p * PAIRB + OFFS);
        float o[8];
#pragma unroll
        for (int c = 0; c < 8; c++) o[c] = 0.0f;
#pragma unroll
        for (int j = 0; j < 16; j++) {
            float s = siP[oi * 17 + j];
            const float4* vr = (const float4*)(vsP + j * 68 + od8 * 8);
            const float4* rr = (const float4*)(rvP + (j - oi + 16) * 68 + od8 * 8);
            float4 v0 = vr[0], v1 = vr[1];
            float4 r0 = rr[0], r1 = rr[1];
            o[0] = fmaf(s, v0.x + r0.x, o[0]);
            o[1] = fmaf(s, v0.y + r0.y, o[1]);
            o[2] = fmaf(s, v0.z + r0.z, o[2]);
            o[3] = fmaf(s, v0.w + r0.w, o[3]);
            o[4] = fmaf(s, v1.x + r1.x, o[4]);
            o[5] = fmaf(s, v1.y + r1.y, o[5]);
            o[6] = fmaf(s, v1.z + r1.z, o[6]);
            o[7] = fmaf(s, v1.w + r1.w, o[7]);
        }
        int hd = blockIdx.y * 4 + p;
        size_t ob = ((size_t)hw * 16 + oi) * QD + hd * 64 + od8 * 8;
#pragma unroll
        for (int c = 0; c < 4; c++) {
            float v0 = o[2 * c], v1 = o[2 * c + 1];
            __nv_bfloat16 h0 = __float2bfloat16(v0);
            __nv_bfloat16 h1 = __float2bfloat16(v1);
            __nv_bfloat16 l0 = __float2bfloat16(v0 - __bfloat162float(h0));
            __nv_bfloat16 l1 = __float2bfloat16(v1 - __bfloat162float(h1));
            *(__nv_bfloat162*)&ATH[ob + 2 * c] = __halves2bfloat162(h0, h1);
            *(__nv_bfloat162*)&ATL[ob + 2 * c] = __halves2bfloat162(l0, l1);
        }
    }
}

// ---------------------------- launcher -------------------------------------
extern "C" void kernel_launch(void* const* d_in, const int* in_sizes, int n_in,
                              void* d_out, int out_size) {
    const float* x     = (const float*)d_in[0];
    const float* Wq    = (const float*)d_in[1];
    const float* Wk    = (const float*)d_in[2];
    const float* Wv    = (const float*)d_in[3];
    const float* Wo    = (const float*)d_in[4];
    const float* bo    = (const float*)d_in[5];
    const float* rel_k = (const float*)d_in[6];
    const float* rel_v = (const float*)d_in[7];
    float* out = (float*)d_out;

    float *v, *qr;
    __nv_bfloat16 *xh, *xl, *qh, *ql, *kh, *kl, *ath, *atl, *wth, *wtl;
    cudaGetSymbolAddress((void**)&v,   g_v);
    cudaGetSymbolAddress((void**)&qr,  g_qr);
    cudaGetSymbolAddress((void**)&xh,  g_xh);
    cudaGetSymbolAddress((void**)&xl,  g_xl);
    cudaGetSymbolAddress((void**)&qh,  g_qh);
    cudaGetSymbolAddress((void**)&ql,  g_ql);
    cudaGetSymbolAddress((void**)&kh,  g_kh);
    cudaGetSymbolAddress((void**)&kl,  g_kl);
    cudaGetSymbolAddress((void**)&ath, g_ath);
    cudaGetSymbolAddress((void**)&atl, g_atl);
    cudaGetSymbolAddress((void**)&wth, g_wth);
    cudaGetSymbolAddress((void**)&wtl, g_wtl);

    // Box path (exact binary64 semantics): SUB_H=15, SUB_W=9
    Boxes bx;
    bx.sub_h = (int)((0.35 - 0.10) * 64.0);
    bx.sub_w = (int)((0.35 - 0.10) * 40.0);
    for (int t = 0; t < TT; t++) {
        double r  = (double)t / 15.0;
        double h0 = 0.10 + r * (0.60 - 0.10);
        double w0 = 0.10 + r * (0.60 - 0.10);
        bx.hs[t] = (int)(h0 * 64.0);
        bx.ws[t] = (int)(w0 * 40.0);
    }

    cudaFuncSetAttribute(gemm_bf, cudaFuncAttributeMaxDynamicSharedMemorySize, GDYN);
    cudaFuncSetAttribute(attn3,   cudaFuncAttributeMaxDynamicSharedMemorySize, ADYN);

    split_x<<<MTOT * QD / 512, 256>>>(x, xh, xl);
    split_w<<<dim3(16, 16, 4), dim3(32, 8)>>>(Wq, Wk, Wv, Wo, wth, wtl);

    gemm_bf<<<dim3(4, 320, 3), 256, GDYN>>>(xh, xl, wth, wtl, nullptr, 0,
                                            qh, ql, kh, kl, v);

    qrel_k<<<dim3(320, 8), 128>>>(qh, ql, rel_k, qr);

    attn3<<<dim3(HW, 2), 128, ADYN>>>(qh, ql, kh, kl, v, qr, rel_v, ath, atl, bx);

    gemm_bf<<<dim3(4, 320, 1), 256, GDYN>>>(ath, atl,
                                            wth + (size_t)3 * QD * QD,
                                            wtl + (size_t)3 * QD * QD,
                                            bo, 3, nullptr, nullptr, nullptr, nullptr, out);
}